// round 9
// baseline (speedup 1.0000x reference)
#include <cuda_runtime.h>
#include <math.h>

#define PH 512
#define PW 512
#define HIDDEN 128
#define ALPHA 1e-4f
#define MAX_CAMS 4096
#define CPB 8
#define TPB 256
#define NFLAGS (MAX_CAMS / CPB)

// Per-camera final 4x4 matrices (row-major), float4-aligned.
__device__ float4 g_table[MAX_CAMS * 4];
// Per-cam-block ready flags (one per CPB cams).
__device__ int g_flag[NFLAGS];

__device__ __forceinline__ float silu_f(float x) {
    return x / (1.0f + expf(-x));
}

__device__ __forceinline__ unsigned long long pack2(float w) {
    unsigned long long r;
    asm("mov.b64 %0, {%1, %1};" : "=l"(r) : "f"(w));
    return r;
}
__device__ __forceinline__ void fma2(unsigned long long& acc,
                                     unsigned long long a,
                                     unsigned long long b) {
    asm("fma.rn.f32x2 %0, %1, %2, %3;" : "=l"(acc) : "l"(a), "l"(b), "l"(acc));
}
__device__ __forceinline__ float lo32(unsigned long long v) {
    return __uint_as_float((unsigned)(v & 0xffffffffull));
}
__device__ __forceinline__ float hi32(unsigned long long v) {
    return __uint_as_float((unsigned)(v >> 32));
}
__device__ __forceinline__ int ld_acquire(const int* p) {
    int v;
    asm volatile("ld.acquire.gpu.global.b32 %0, [%1];"
                 : "=r"(v) : "l"(p) : "memory");
    return v;
}
__device__ __forceinline__ void st_release(int* p, int v) {
    asm volatile("st.release.gpu.global.b32 [%0], %1;"
                 :: "l"(p), "r"(v) : "memory");
}

__global__ void zero_flags_kernel() {
    if (threadIdx.x < NFLAGS) g_flag[threadIdx.x] = 0;
}

// ---------------------------------------------------------------------------
// Fused producer/consumer kernel.
// Phase 1 (producer): tri-plane sampling + MLP + Rodrigues + c2w @ init_c2w
//   for this block's 8 cams (identical math to the 43.6us R6 kernel).
//   Publish table rows via threadfence + release flag.
// Phase 2 (consumer): this block's slice of the ray scatter; acquire-spin on
//   the producing block's flag per camera (almost always already set).
// All blocks are resident in one wave (512 <= 4*148), so spinning can never
// deadlock: every producer is always running.
// ---------------------------------------------------------------------------
__global__ void __launch_bounds__(TPB, 4) fused_kernel(
    const float* __restrict__ t,
    const float* __restrict__ pxy,
    const float* __restrict__ pxz,
    const float* __restrict__ pyz,
    const float* __restrict__ w1, const float* __restrict__ b1,
    const float* __restrict__ w2, const float* __restrict__ b2,
    const float* __restrict__ w3, const float* __restrict__ b3,
    const float* __restrict__ init_c2w,
    const int* __restrict__ cam_id,
    float4* __restrict__ out,
    int num_cams, int n4, int stride)
{
    int cam0 = blockIdx.x * CPB;
    int tid = threadIdx.x;
    int warp = tid >> 5;
    int lane = tid & 31;
    int half = tid >> 7;
    int htid = tid & 127;

    __shared__ float s_ts[CPB][4];
    __shared__ float s_codes[96][CPB];
    __shared__ unsigned long long s_p1[2][HIDDEN][4];
    __shared__ float s_h1[HIDDEN][CPB];
    __shared__ unsigned long long s_p2[2][HIDDEN][4];
    __shared__ float s_h2[HIDDEN][CPB];
    __shared__ float s_part[CPB * 3][2];
    __shared__ float s_rot[CPB][3];

    // ======================= PHASE 1: producer =======================
    if (cam0 < num_cams) {
        if (tid < CPB * 3) {
            int c = tid / 3, a = tid % 3;
            int cam = cam0 + c;
            s_ts[c][a] = (cam < num_cams) ? __ldg(t + cam * 3 + a) : 0.0f;
        }
        __syncthreads();

        // ---- sampling: tasks 0..23, cam=task/3, plane=task%3 ----
        #pragma unroll
        for (int i = 0; i < 3; i++) {
            int task = warp * 3 + i;
            int c = task / 3;
            int p = task - c * 3;
            int cam = cam0 + c;
            float cx, cy;
            const float* plane;
            if (p == 0)      { plane = pxy; cx = s_ts[c][0]; cy = s_ts[c][1]; }
            else if (p == 1) { plane = pxz; cx = s_ts[c][0]; cy = s_ts[c][2]; }
            else             { plane = pyz; cx = s_ts[c][1]; cy = s_ts[c][2]; }

            float x = (cx + 1.0f) * 0.5f * (float)(PW - 1);
            float y = (cy + 1.0f) * 0.5f * (float)(PH - 1);
            float x0f = floorf(x), y0f = floorf(y);
            float wx = x - x0f, wy = y - y0f;
            int x0 = min(max((int)x0f, 0), PW - 1);
            int x1 = min(max((int)x0f + 1, 0), PW - 1);
            int y0 = min(max((int)y0f, 0), PH - 1);
            int y1 = min(max((int)y0f + 1, 0), PH - 1);

            const float* pc = plane + (size_t)lane * (PH * PW);
            float v00 = __ldg(pc + y0 * PW + x0);
            float v01 = __ldg(pc + y0 * PW + x1);
            float v10 = __ldg(pc + y1 * PW + x0);
            float v11 = __ldg(pc + y1 * PW + x1);

            float r = v00 * (1.0f - wx) * (1.0f - wy)
                    + v01 * wx * (1.0f - wy)
                    + v10 * (1.0f - wx) * wy
                    + v11 * wx * wy;
            s_codes[p * 32 + lane][c] = (cam < num_cams) ? r : 0.0f;
        }
        __syncthreads();

        // ---- Layer 1: k-split 48/48, f32x2 ----
        {
            unsigned long long acc[4] = {0ull, 0ull, 0ull, 0ull};
            int k0 = half * 48;
            #pragma unroll 4
            for (int k = k0; k < k0 + 48; k++) {
                unsigned long long wp = pack2(__ldg(w1 + k * HIDDEN + htid));
                const ulonglong2* row = (const ulonglong2*)&s_codes[k][0];
                ulonglong2 q0 = row[0];
                ulonglong2 q1 = row[1];
                fma2(acc[0], q0.x, wp);
                fma2(acc[1], q0.y, wp);
                fma2(acc[2], q1.x, wp);
                fma2(acc[3], q1.y, wp);
            }
            #pragma unroll
            for (int j = 0; j < 4; j++) s_p1[half][htid][j] = acc[j];
        }
        __syncthreads();
        {
            #pragma unroll
            for (int j = 0; j < 2; j++) {
                int pairidx = tid + 256 * j;
                int hid = pairidx >> 2;
                int pr = pairidx & 3;
                float bv = __ldg(b1 + hid);
                unsigned long long a = s_p1[0][hid][pr];
                unsigned long long b = s_p1[1][hid][pr];
                s_h1[hid][pr * 2 + 0] = silu_f(lo32(a) + lo32(b) + bv);
                s_h1[hid][pr * 2 + 1] = silu_f(hi32(a) + hi32(b) + bv);
            }
        }
        __syncthreads();

        // ---- Layer 2: k-split 64/64 ----
        {
            unsigned long long acc[4] = {0ull, 0ull, 0ull, 0ull};
            int k0 = half * 64;
            #pragma unroll 4
            for (int k = k0; k < k0 + 64; k++) {
                unsigned long long wp = pack2(__ldg(w2 + k * HIDDEN + htid));
                const ulonglong2* row = (const ulonglong2*)&s_h1[k][0];
                ulonglong2 q0 = row[0];
                ulonglong2 q1 = row[1];
                fma2(acc[0], q0.x, wp);
                fma2(acc[1], q0.y, wp);
                fma2(acc[2], q1.x, wp);
                fma2(acc[3], q1.y, wp);
            }
            #pragma unroll
            for (int j = 0; j < 4; j++) s_p2[half][htid][j] = acc[j];
        }
        __syncthreads();
        {
            #pragma unroll
            for (int j = 0; j < 2; j++) {
                int pairidx = tid + 256 * j;
                int hid = pairidx >> 2;
                int pr = pairidx & 3;
                float bv = __ldg(b2 + hid);
                unsigned long long a = s_p2[0][hid][pr];
                unsigned long long b = s_p2[1][hid][pr];
                s_h2[hid][pr * 2 + 0] = silu_f(lo32(a) + lo32(b) + bv);
                s_h2[hid][pr * 2 + 1] = silu_f(hi32(a) + hi32(b) + bv);
            }
        }
        __syncthreads();

        // ---- Layer 3 ----
        if (tid < CPB * 3 * 2) {
            int out_idx = tid >> 1;
            int h = tid & 1;
            int c = out_idx / 3, m = out_idx % 3;
            float acc = 0.0f;
            int k0 = h * 64;
            #pragma unroll 8
            for (int k = k0; k < k0 + 64; k++)
                acc = fmaf(s_h2[k][c], __ldg(w3 + k * 3 + m), acc);
            s_part[out_idx][h] = acc;
        }
        __syncthreads();
        if (tid < CPB * 3) {
            int c = tid / 3, m = tid % 3;
            s_rot[c][m] = (s_part[tid][0] + s_part[tid][1] + __ldg(b3 + m)) * ALPHA;
        }
        __syncthreads();

        // ---- Rodrigues + compose, one camera per thread ----
        if (tid < CPB) {
            int cam = cam0 + tid;
            if (cam < num_cams) {
                float rx = s_rot[tid][0], ry = s_rot[tid][1], rz = s_rot[tid][2];
                float th2 = rx * rx + ry * ry + rz * rz;
                float th = sqrtf(th2);
                float A = sinf(th) / (th + 1e-10f);
                float B = (1.0f - cosf(th)) / (th2 + 1e-10f);
                float R00 = 1.0f - B * (ry * ry + rz * rz);
                float R01 = -A * rz + B * (rx * ry);
                float R02 =  A * ry + B * (rx * rz);
                float R10 =  A * rz + B * (rx * ry);
                float R11 = 1.0f - B * (rx * rx + rz * rz);
                float R12 = -A * rx + B * (ry * rz);
                float R20 = -A * ry + B * (rx * rz);
                float R21 =  A * rx + B * (ry * rz);
                float R22 = 1.0f - B * (rx * rx + ry * ry);

                float tx = s_ts[tid][0], ty = s_ts[tid][1], tz = s_ts[tid][2];
                float C[3][4] = {
                    {R00, R01, R02, tx},
                    {R10, R11, R12, ty},
                    {R20, R21, R22, tz}
                };
                const float* M = init_c2w + (size_t)cam * 16;
                float* o = (float*)(g_table + cam * 4);
                #pragma unroll
                for (int i = 0; i < 3; i++) {
                    #pragma unroll
                    for (int j = 0; j < 4; j++) {
                        o[i * 4 + j] = C[i][0] * __ldg(M + j)
                                     + C[i][1] * __ldg(M + 4 + j)
                                     + C[i][2] * __ldg(M + 8 + j)
                                     + C[i][3] * __ldg(M + 12 + j);
                    }
                }
                o[12] = __ldg(M + 12);
                o[13] = __ldg(M + 13);
                o[14] = __ldg(M + 14);
                o[15] = __ldg(M + 15);
            }
            __threadfence();   // make this thread's table stores gpu-visible
        }
        __syncthreads();
        if (tid == 0) st_release(&g_flag[blockIdx.x], 1);
    } else {
        __syncthreads();   // keep barrier counts trivially consistent
        if (tid == 0) st_release(&g_flag[blockIdx.x], 1);
    }

    // ======================= PHASE 2: consumer =======================
    // Block's slice of scatter: ILP4 pattern, acquire-spin per camera flag.
    {
        int per_block = (stride + gridDim.x - 1) / gridDim.x;
        int base = blockIdx.x * per_block;
        for (int i0 = base + tid; i0 < base + per_block; i0 += TPB) {
            int idx[4];
            int cid[4];
            bool pred[4];
            #pragma unroll
            for (int j = 0; j < 4; j++) {
                idx[j] = i0 + j * stride;
                pred[j] = idx[j] < n4;
                cid[j] = pred[j] ? __ldg(cam_id + (idx[j] >> 2)) : 0;
            }
            #pragma unroll
            for (int j = 0; j < 4; j++) {
                while (ld_acquire(&g_flag[cid[j] >> 3]) == 0) __nanosleep(32);
            }
            float4 v[4];
            #pragma unroll
            for (int j = 0; j < 4; j++)
                v[j] = __ldg(&g_table[cid[j] * 4 + (idx[j] & 3)]);
            #pragma unroll
            for (int j = 0; j < 4; j++)
                if (pred[j]) __stcs(&out[idx[j]], v[j]);
        }
    }
}

extern "C" void kernel_launch(void* const* d_in, const int* in_sizes, int n_in,
                              void* d_out, int out_size) {
    const int*   cam_id   = (const int*)d_in[0];
    const float* t        = (const float*)d_in[1];
    const float* pxy      = (const float*)d_in[2];
    const float* pxz      = (const float*)d_in[3];
    const float* pyz      = (const float*)d_in[4];
    const float* w1       = (const float*)d_in[5];
    const float* b1       = (const float*)d_in[6];
    const float* w2       = (const float*)d_in[7];
    const float* b2       = (const float*)d_in[8];
    const float* w3       = (const float*)d_in[9];
    const float* b3       = (const float*)d_in[10];
    const float* init_c2w = (const float*)d_in[11];

    int n_rays = in_sizes[0];
    int num_cams = in_sizes[1] / 3;
    if (num_cams > MAX_CAMS) num_cams = MAX_CAMS;

    zero_flags_kernel<<<1, NFLAGS>>>();

    int nblk = (num_cams + CPB - 1) / CPB;      // 512 for 4096 cams
    int n4 = n_rays * 4;
    int stride = (n4 + 3) / 4;                  // ILP4 slice stride
    fused_kernel<<<nblk, TPB>>>(t, pxy, pxz, pyz, w1, b1, w2, b2, w3, b3,
                                init_c2w, cam_id, (float4*)d_out,
                                num_cams, n4, stride);
}

// round 11
// speedup vs baseline: 2.3260x; 2.3260x over previous
#include <cuda_runtime.h>
#include <math.h>

#define PH 512
#define PW 512
#define HIDDEN 128
#define ALPHA 1e-4f
#define MAX_CAMS 4096
#define CPB 8
#define TPB 256

// Per-camera final 4x4 matrices (row-major), float4-aligned.
__device__ float4 g_table[MAX_CAMS * 4];

__device__ __forceinline__ float silu_f(float x) {
    return x / (1.0f + expf(-x));
}

__device__ __forceinline__ unsigned long long pack2(float w) {
    unsigned long long r;
    asm("mov.b64 %0, {%1, %1};" : "=l"(r) : "f"(w));
    return r;
}
__device__ __forceinline__ void fma2(unsigned long long& acc,
                                     unsigned long long a,
                                     unsigned long long b) {
    asm("fma.rn.f32x2 %0, %1, %2, %3;" : "=l"(acc) : "l"(a), "l"(b), "l"(acc));
}
__device__ __forceinline__ float lo32(unsigned long long v) {
    return __uint_as_float((unsigned)(v & 0xffffffffull));
}
__device__ __forceinline__ float hi32(unsigned long long v) {
    return __uint_as_float((unsigned)(v >> 32));
}

// L2 evict-last via cache-hint policy (the form this ptxas accepts for
// scalar/v4 loads). Pins hot plane sectors / table lines in L2 across
// graph replays; the output stream is evict-first via __stcs.
__device__ __forceinline__ unsigned long long keep_policy() {
    unsigned long long p;
    asm("createpolicy.fractional.L2::evict_last.b64 %0, 1.0;" : "=l"(p));
    return p;
}
__device__ __forceinline__ float ldg_keep(const float* p, unsigned long long pol) {
    float v;
    asm volatile("ld.global.nc.L2::cache_hint.f32 %0, [%1], %2;"
                 : "=f"(v) : "l"(p), "l"(pol));
    return v;
}
__device__ __forceinline__ float4 ldg_keep4(const float4* p, unsigned long long pol) {
    float4 v;
    asm volatile("ld.global.nc.L2::cache_hint.v4.f32 {%0,%1,%2,%3}, [%4], %5;"
                 : "=f"(v.x), "=f"(v.y), "=f"(v.z), "=f"(v.w)
                 : "l"(p), "l"(pol));
    return v;
}

// ---------------------------------------------------------------------------
// Fused kernel: tri-plane sampling + MLP + Rodrigues + c2w @ init_c2w.
// 8 cams per 256-thread block (R6 known-good math; plane loads evict_last).
// ---------------------------------------------------------------------------
__global__ void __launch_bounds__(TPB) cam_kernel(
    const float* __restrict__ t,
    const float* __restrict__ pxy,
    const float* __restrict__ pxz,
    const float* __restrict__ pyz,
    const float* __restrict__ w1, const float* __restrict__ b1,
    const float* __restrict__ w2, const float* __restrict__ b2,
    const float* __restrict__ w3, const float* __restrict__ b3,
    const float* __restrict__ init_c2w,
    int num_cams)
{
    int cam0 = blockIdx.x * CPB;
    int tid = threadIdx.x;
    int warp = tid >> 5;
    int lane = tid & 31;
    int half = tid >> 7;         // k-split half
    int htid = tid & 127;        // hidden unit index

    __shared__ float s_ts[CPB][4];
    __shared__ float s_codes[96][CPB];           // [k][cam], cam-minor for f32x2
    __shared__ unsigned long long s_p1[2][HIDDEN][4];
    __shared__ float s_h1[HIDDEN][CPB];
    __shared__ unsigned long long s_p2[2][HIDDEN][4];
    __shared__ float s_h2[HIDDEN][CPB];
    __shared__ float s_part[CPB * 3][2];
    __shared__ float s_rot[CPB][3];

    unsigned long long pol = keep_policy();

    if (tid < CPB * 3) {
        int c = tid / 3, a = tid % 3;
        int cam = cam0 + c;
        s_ts[c][a] = (cam < num_cams) ? __ldg(t + cam * 3 + a) : 0.0f;
    }
    __syncthreads();

    // ---- Phase A: sampling. Tasks 0..23: cam=task/3, plane=task%3. ----
    #pragma unroll
    for (int i = 0; i < 3; i++) {
        int task = warp * 3 + i;
        int c = task / 3;
        int p = task - c * 3;
        int cam = cam0 + c;
        float cx, cy;
        const float* plane;
        if (p == 0)      { plane = pxy; cx = s_ts[c][0]; cy = s_ts[c][1]; }
        else if (p == 1) { plane = pxz; cx = s_ts[c][0]; cy = s_ts[c][2]; }
        else             { plane = pyz; cx = s_ts[c][1]; cy = s_ts[c][2]; }

        float x = (cx + 1.0f) * 0.5f * (float)(PW - 1);
        float y = (cy + 1.0f) * 0.5f * (float)(PH - 1);
        float x0f = floorf(x), y0f = floorf(y);
        float wx = x - x0f, wy = y - y0f;
        int x0 = min(max((int)x0f, 0), PW - 1);
        int x1 = min(max((int)x0f + 1, 0), PW - 1);
        int y0 = min(max((int)y0f, 0), PH - 1);
        int y1 = min(max((int)y0f + 1, 0), PH - 1);

        const float* pc = plane + (size_t)lane * (PH * PW);
        float v00 = ldg_keep(pc + y0 * PW + x0, pol);
        float v01 = ldg_keep(pc + y0 * PW + x1, pol);
        float v10 = ldg_keep(pc + y1 * PW + x0, pol);
        float v11 = ldg_keep(pc + y1 * PW + x1, pol);

        float r = v00 * (1.0f - wx) * (1.0f - wy)
                + v01 * wx * (1.0f - wy)
                + v10 * (1.0f - wx) * wy
                + v11 * wx * wy;
        s_codes[p * 32 + lane][c] = (cam < num_cams) ? r : 0.0f;
    }
    __syncthreads();

    // ---- Layer 1: codes(96) @ w1(96,128), k-split 48/48, f32x2 packed ----
    {
        unsigned long long acc[4] = {0ull, 0ull, 0ull, 0ull};
        int k0 = half * 48;
        #pragma unroll 4
        for (int k = k0; k < k0 + 48; k++) {
            unsigned long long wp = pack2(__ldg(w1 + k * HIDDEN + htid));
            const ulonglong2* row = (const ulonglong2*)&s_codes[k][0];
            ulonglong2 q0 = row[0];
            ulonglong2 q1 = row[1];
            fma2(acc[0], q0.x, wp);
            fma2(acc[1], q0.y, wp);
            fma2(acc[2], q1.x, wp);
            fma2(acc[3], q1.y, wp);
        }
        #pragma unroll
        for (int j = 0; j < 4; j++) s_p1[half][htid][j] = acc[j];
    }
    __syncthreads();
    {
        #pragma unroll
        for (int j = 0; j < 2; j++) {
            int pairidx = tid + 256 * j;     // 0..511
            int hid = pairidx >> 2;
            int pr = pairidx & 3;
            float bv = __ldg(b1 + hid);
            unsigned long long a = s_p1[0][hid][pr];
            unsigned long long b = s_p1[1][hid][pr];
            s_h1[hid][pr * 2 + 0] = silu_f(lo32(a) + lo32(b) + bv);
            s_h1[hid][pr * 2 + 1] = silu_f(hi32(a) + hi32(b) + bv);
        }
    }
    __syncthreads();

    // ---- Layer 2: h1(128) @ w2(128,128), k-split 64/64 ----
    {
        unsigned long long acc[4] = {0ull, 0ull, 0ull, 0ull};
        int k0 = half * 64;
        #pragma unroll 4
        for (int k = k0; k < k0 + 64; k++) {
            unsigned long long wp = pack2(__ldg(w2 + k * HIDDEN + htid));
            const ulonglong2* row = (const ulonglong2*)&s_h1[k][0];
            ulonglong2 q0 = row[0];
            ulonglong2 q1 = row[1];
            fma2(acc[0], q0.x, wp);
            fma2(acc[1], q0.y, wp);
            fma2(acc[2], q1.x, wp);
            fma2(acc[3], q1.y, wp);
        }
        #pragma unroll
        for (int j = 0; j < 4; j++) s_p2[half][htid][j] = acc[j];
    }
    __syncthreads();
    {
        #pragma unroll
        for (int j = 0; j < 2; j++) {
            int pairidx = tid + 256 * j;
            int hid = pairidx >> 2;
            int pr = pairidx & 3;
            float bv = __ldg(b2 + hid);
            unsigned long long a = s_p2[0][hid][pr];
            unsigned long long b = s_p2[1][hid][pr];
            s_h2[hid][pr * 2 + 0] = silu_f(lo32(a) + lo32(b) + bv);
            s_h2[hid][pr * 2 + 1] = silu_f(hi32(a) + hi32(b) + bv);
        }
    }
    __syncthreads();

    // ---- Layer 3: h2(128) @ w3(128,3) + b3, * ALPHA. 48 outs x 2 k-halves ----
    if (tid < CPB * 3 * 2) {
        int out_idx = tid >> 1;
        int h = tid & 1;
        int c = out_idx / 3, m = out_idx % 3;
        float acc = 0.0f;
        int k0 = h * 64;
        #pragma unroll 8
        for (int k = k0; k < k0 + 64; k++)
            acc = fmaf(s_h2[k][c], __ldg(w3 + k * 3 + m), acc);
        s_part[out_idx][h] = acc;
    }
    __syncthreads();
    if (tid < CPB * 3) {
        int c = tid / 3, m = tid % 3;
        s_rot[c][m] = (s_part[tid][0] + s_part[tid][1] + __ldg(b3 + m)) * ALPHA;
    }
    __syncthreads();

    // ---- Rodrigues + [R|t;0001] @ init_c2w, one camera per thread ----
    if (tid < CPB) {
        int cam = cam0 + tid;
        if (cam < num_cams) {
            float rx = s_rot[tid][0], ry = s_rot[tid][1], rz = s_rot[tid][2];
            float th2 = rx * rx + ry * ry + rz * rz;
            float th = sqrtf(th2);
            float A = sinf(th) / (th + 1e-10f);
            float B = (1.0f - cosf(th)) / (th2 + 1e-10f);
            float R00 = 1.0f - B * (ry * ry + rz * rz);
            float R01 = -A * rz + B * (rx * ry);
            float R02 =  A * ry + B * (rx * rz);
            float R10 =  A * rz + B * (rx * ry);
            float R11 = 1.0f - B * (rx * rx + rz * rz);
            float R12 = -A * rx + B * (ry * rz);
            float R20 = -A * ry + B * (rx * rz);
            float R21 =  A * rx + B * (ry * rz);
            float R22 = 1.0f - B * (rx * rx + ry * ry);

            float tx = s_ts[tid][0], ty = s_ts[tid][1], tz = s_ts[tid][2];
            float C[3][4] = {
                {R00, R01, R02, tx},
                {R10, R11, R12, ty},
                {R20, R21, R22, tz}
            };
            const float* M = init_c2w + (size_t)cam * 16;
            float* o = (float*)(g_table + cam * 4);
            #pragma unroll
            for (int i = 0; i < 3; i++) {
                #pragma unroll
                for (int j = 0; j < 4; j++) {
                    o[i * 4 + j] = C[i][0] * __ldg(M + j)
                                 + C[i][1] * __ldg(M + 4 + j)
                                 + C[i][2] * __ldg(M + 8 + j)
                                 + C[i][3] * __ldg(M + 12 + j);
                }
            }
            o[12] = __ldg(M + 12);
            o[13] = __ldg(M + 13);
            o[14] = __ldg(M + 14);
            o[15] = __ldg(M + 15);
        }
    }
}

// ---------------------------------------------------------------------------
// Scatter: 8-way ILP, evict-last table gathers, evict-first output stores.
// ---------------------------------------------------------------------------
#define SC_ILP 8
__global__ void __launch_bounds__(256) scatter_kernel(
    const int* __restrict__ cam_id,
    float4* __restrict__ out,
    int n4, int stride)
{
    int i = blockIdx.x * 256 + threadIdx.x;
    unsigned long long pol = keep_policy();

    int idx[SC_ILP];
    int cid[SC_ILP];
    float4 v[SC_ILP];
    bool pred[SC_ILP];

    #pragma unroll
    for (int j = 0; j < SC_ILP; j++) {
        idx[j] = i + j * stride;
        pred[j] = idx[j] < n4;
        cid[j] = pred[j] ? __ldg(cam_id + (idx[j] >> 2)) : 0;
    }
    #pragma unroll
    for (int j = 0; j < SC_ILP; j++) {
        v[j] = ldg_keep4(&g_table[cid[j] * 4 + (idx[j] & 3)], pol);
    }
    #pragma unroll
    for (int j = 0; j < SC_ILP; j++) {
        if (pred[j]) __stcs(&out[idx[j]], v[j]);
    }
}

extern "C" void kernel_launch(void* const* d_in, const int* in_sizes, int n_in,
                              void* d_out, int out_size) {
    const int*   cam_id   = (const int*)d_in[0];
    const float* t        = (const float*)d_in[1];
    const float* pxy      = (const float*)d_in[2];
    const float* pxz      = (const float*)d_in[3];
    const float* pyz      = (const float*)d_in[4];
    const float* w1       = (const float*)d_in[5];
    const float* b1       = (const float*)d_in[6];
    const float* w2       = (const float*)d_in[7];
    const float* b2       = (const float*)d_in[8];
    const float* w3       = (const float*)d_in[9];
    const float* b3       = (const float*)d_in[10];
    const float* init_c2w = (const float*)d_in[11];

    int n_rays = in_sizes[0];
    int num_cams = in_sizes[1] / 3;
    if (num_cams > MAX_CAMS) num_cams = MAX_CAMS;

    int nblk1 = (num_cams + CPB - 1) / CPB;
    cam_kernel<<<nblk1, TPB>>>(t, pxy, pxz, pyz, w1, b1, w2, b2, w3, b3,
                               init_c2w, num_cams);

    int n4 = n_rays * 4;
    int stride = (n4 + SC_ILP - 1) / SC_ILP;
    int nblk_sc = (stride + 255) / 256;
    scatter_kernel<<<nblk_sc, 256>>>(cam_id, (float4*)d_out, n4, stride);
}